// round 15
// baseline (speedup 1.0000x reference)
#include <cuda_runtime.h>
#include <cuda_bf16.h>
#include <cstdint>

#define BB 4
#define SS 1024
#define HH 16
#define DKK 64
#define DD 1024
#define MTOT (BB*SS)

// ---------------- scratch (device globals; no allocations allowed) ----------
__device__ float g_q[BB*HH*SS*DKK];   // [b,h,s,dk]
__device__ float g_k[BB*HH*SS*DKK];
__device__ float g_v[BB*HH*SS*DKK];
__device__ float g_ctx[MTOT*DD];      // [b*S+s, h*64+dh]

// ---------------- tf32 helpers ----------------------------------------------
__device__ __forceinline__ uint32_t f2tf(float f) {
    uint32_t r;
    asm("cvt.rna.tf32.f32 %0, %1;" : "=r"(r) : "f"(f));
    return r;
}

__device__ __forceinline__ void mma_tf32(float c[4], const uint32_t a[4], const uint32_t b[2]) {
    asm("mma.sync.aligned.m16n8k8.row.col.f32.tf32.tf32.f32 "
        "{%0,%1,%2,%3},{%4,%5,%6,%7},{%8,%9},{%0,%1,%2,%3};"
        : "+f"(c[0]), "+f"(c[1]), "+f"(c[2]), "+f"(c[3])
        : "r"(a[0]), "r"(a[1]), "r"(a[2]), "r"(a[3]), "r"(b[0]), "r"(b[1]));
}

// ---------------- generic 128x128 tf32 GEMM body: C = X @ W^T + bias --------
// X: [M,1024] row-major.  W: [N,1024] row-major (so B is col-major [k][n]).
// headsplit=true: store to out4d[b][h][s][dh] with m=b*1024+s, n=h*64+dh.
// headsplit=false: store row-major to outRM[m*1024+n].
__device__ __forceinline__ void gemm_body(
    const float* __restrict__ X, const float* __restrict__ W,
    const float* __restrict__ bias,
    float* out4d, float* outRM, bool headsplit,
    float (*As)[36], float (*Bs)[36])
{
    const int tid  = threadIdx.x;
    const int wid  = tid >> 5;
    const int lane = tid & 31;
    const int g    = lane >> 2;
    const int t    = lane & 3;
    const int wm   = (wid >> 2) * 64;   // warp m offset (2 rows of warps)
    const int wn   = (wid & 3) * 32;    // warp n offset (4 cols of warps)
    const int m0   = blockIdx.y * 128;
    const int n0   = blockIdx.x * 128;

    float acc[4][4][4] = {};

    for (int k0 = 0; k0 < 1024; k0 += 32) {
        __syncthreads();
        // load 128x32 of X and 128x32 of W (as [n][k]) into smem, float4
        #pragma unroll
        for (int p = 0; p < 4; p++) {
            int i  = tid + p * 256;
            int r  = i >> 3;
            int c4 = (i & 7) * 4;
            float4 va = *(const float4*)(X + (size_t)(m0 + r) * 1024 + k0 + c4);
            *(float4*)(&As[r][c4]) = va;
            float4 vb = *(const float4*)(W + (size_t)(n0 + r) * 1024 + k0 + c4);
            *(float4*)(&Bs[r][c4]) = vb;
        }
        __syncthreads();

        #pragma unroll
        for (int ks = 0; ks < 4; ks++) {
            const int k = ks * 8;
            uint32_t af[4][4], bf[4][2];
            #pragma unroll
            for (int im = 0; im < 4; im++) {
                int r = wm + im * 16 + g;
                af[im][0] = f2tf(As[r    ][k + t    ]);
                af[im][1] = f2tf(As[r + 8][k + t    ]);
                af[im][2] = f2tf(As[r    ][k + t + 4]);
                af[im][3] = f2tf(As[r + 8][k + t + 4]);
            }
            #pragma unroll
            for (int in_ = 0; in_ < 4; in_++) {
                int c = wn + in_ * 8 + g;
                bf[in_][0] = f2tf(Bs[c][k + t    ]);
                bf[in_][1] = f2tf(Bs[c][k + t + 4]);
            }
            #pragma unroll
            for (int im = 0; im < 4; im++)
                #pragma unroll
                for (int in_ = 0; in_ < 4; in_++)
                    mma_tf32(acc[im][in_], af[im], bf[in_]);
        }
    }

    // epilogue
    #pragma unroll
    for (int im = 0; im < 4; im++) {
        #pragma unroll
        for (int in_ = 0; in_ < 4; in_++) {
            int r0 = m0 + wm + im * 16 + g;
            int c0 = n0 + wn + in_ * 8 + t * 2;
            float bv0 = bias[c0], bv1 = bias[c0 + 1];
            float v00 = acc[im][in_][0] + bv0;
            float v01 = acc[im][in_][1] + bv1;
            float v10 = acc[im][in_][2] + bv0;
            float v11 = acc[im][in_][3] + bv1;
            if (headsplit) {
                #pragma unroll
                for (int rr = 0; rr < 2; rr++) {
                    int r = r0 + rr * 8;
                    int b = r >> 10, s = r & 1023;
                    int h = c0 >> 6, dh = c0 & 63;
                    size_t addr = ((((size_t)b * HH + h) * SS + s) * DKK + dh);
                    float2 v = rr ? make_float2(v10, v11) : make_float2(v00, v01);
                    *(float2*)(out4d + addr) = v;
                }
            } else {
                *(float2*)(outRM + (size_t)r0 * 1024 + c0)       = make_float2(v00, v01);
                *(float2*)(outRM + (size_t)(r0 + 8) * 1024 + c0) = make_float2(v10, v11);
            }
        }
    }
}

__global__ __launch_bounds__(256) void gemm_qkv(
    const float* __restrict__ Qin, const float* __restrict__ Kin, const float* __restrict__ Vin,
    const float* __restrict__ Wq, const float* __restrict__ Wk, const float* __restrict__ Wv,
    const float* __restrict__ bq, const float* __restrict__ bk, const float* __restrict__ bv)
{
    __shared__ float As[128][36];
    __shared__ float Bs[128][36];
    const float* X; const float* W; const float* bias; float* out;
    if (blockIdx.z == 0)      { X = Qin; W = Wq; bias = bq; out = g_q; }
    else if (blockIdx.z == 1) { X = Kin; W = Wk; bias = bk; out = g_k; }
    else                      { X = Vin; W = Wv; bias = bv; out = g_v; }
    gemm_body(X, W, bias, out, nullptr, true, As, Bs);
}

__global__ __launch_bounds__(256) void gemm_out(
    const float* __restrict__ Wo, const float* __restrict__ bo, float* __restrict__ out)
{
    __shared__ float As[128][36];
    __shared__ float Bs[128][36];
    gemm_body(g_ctx, Wo, bo, nullptr, out, false, As, Bs);
}

// ---------------- attention kernel ------------------------------------------
// One CTA per (b, h, 32-row query tile). 256 threads (8 warps).
// smem: Qs[32][68], Ks[128][68] (reused for V), Sc[32][1032]
#define QS_ELEMS   (32 * 68)
#define KS_ELEMS   (128 * 68)
#define SC_ELEMS   (32 * 1032)
#define ATTN_SMEM  ((QS_ELEMS + KS_ELEMS + SC_ELEMS) * 4)

__global__ __launch_bounds__(256, 1) void attn_kernel(float* __restrict__ attn_out, int write_attn)
{
    extern __shared__ float sm[];
    float (*Qs)[68]   = (float(*)[68])sm;
    float (*Ks)[68]   = (float(*)[68])(sm + QS_ELEMS);
    float (*Sc)[1032] = (float(*)[1032])(sm + QS_ELEMS + KS_ELEMS);

    const int tid  = threadIdx.x;
    const int wid  = tid >> 5;
    const int lane = tid & 31;
    const int g    = lane >> 2;
    const int t    = lane & 3;
    const int b    = blockIdx.z;
    const int h    = blockIdx.y;
    const int qt   = gridDim.x - 1 - blockIdx.x;   // heavy tiles launch first
    const int q0   = qt * 32;

    const size_t bh = (size_t)b * HH + h;
    const float* qbase = g_q + bh * SS * DKK;
    const float* kbase = g_k + bh * SS * DKK;
    const float* vbase = g_v + bh * SS * DKK;

    // load Q tile (32 x 64)
    for (int i = tid; i < 32 * 16; i += 256) {
        int r = i >> 4, c4 = (i & 15) * 4;
        *(float4*)(&Qs[r][c4]) = *(const float4*)(qbase + (size_t)(q0 + r) * DKK + c4);
    }

    const int kmax = q0 + 32;
    const int nch  = (kmax + 127) >> 7;

    // ---------------- phase 1: scores = Q K^T / 8 into Sc -------------------
    for (int kc = 0; kc < nch; kc++) {
        __syncthreads();
        for (int i = tid; i < 128 * 16; i += 256) {
            int r = i >> 4, c4 = (i & 15) * 4;
            *(float4*)(&Ks[r][c4]) = *(const float4*)(kbase + (size_t)(kc * 128 + r) * DKK + c4);
        }
        __syncthreads();

        float acc[2][2][4] = {};
        #pragma unroll
        for (int ks = 0; ks < 8; ks++) {
            const int k = ks * 8;
            uint32_t af[2][4], bf[2][2];
            #pragma unroll
            for (int im = 0; im < 2; im++) {
                int r = im * 16 + g;
                af[im][0] = f2tf(Qs[r    ][k + t    ]);
                af[im][1] = f2tf(Qs[r + 8][k + t    ]);
                af[im][2] = f2tf(Qs[r    ][k + t + 4]);
                af[im][3] = f2tf(Qs[r + 8][k + t + 4]);
            }
            #pragma unroll
            for (int in_ = 0; in_ < 2; in_++) {
                int c = wid * 16 + in_ * 8 + g;
                bf[in_][0] = f2tf(Ks[c][k + t    ]);
                bf[in_][1] = f2tf(Ks[c][k + t + 4]);
            }
            #pragma unroll
            for (int im = 0; im < 2; im++)
                #pragma unroll
                for (int in_ = 0; in_ < 2; in_++)
                    mma_tf32(acc[im][in_], af[im], bf[in_]);
        }
        // store scaled scores
        #pragma unroll
        for (int im = 0; im < 2; im++) {
            #pragma unroll
            for (int in_ = 0; in_ < 2; in_++) {
                int r = im * 16 + g;
                int c = kc * 128 + wid * 16 + in_ * 8 + t * 2;
                *(float2*)(&Sc[r    ][c]) = make_float2(acc[im][in_][0] * 0.125f, acc[im][in_][1] * 0.125f);
                *(float2*)(&Sc[r + 8][c]) = make_float2(acc[im][in_][2] * 0.125f, acc[im][in_][3] * 0.125f);
            }
        }
    }
    __syncthreads();

    // ---------------- phase 2: causal softmax + write attn ------------------
    #pragma unroll
    for (int rr = 0; rr < 4; rr++) {
        const int m   = wid + rr * 8;     // each warp owns 4 rows
        const int q   = q0 + m;
        const int lim = q + 1;            // keys 0..q valid

        float mx = -3.4e38f;
        for (int c = lane; c < lim; c += 32) mx = fmaxf(mx, Sc[m][c]);
        #pragma unroll
        for (int o = 16; o; o >>= 1) mx = fmaxf(mx, __shfl_xor_sync(0xffffffffu, mx, o));

        float s = 0.f;
        for (int c = lane; c < lim; c += 32) {
            float e = __expf(Sc[m][c] - mx);
            Sc[m][c] = e;
            s += e;
        }
        #pragma unroll
        for (int o = 16; o; o >>= 1) s += __shfl_xor_sync(0xffffffffu, s, o);
        const float rinv = 1.0f / s;

        float* arow = attn_out + (bh * SS + (size_t)q) * SS;
        for (int c = lane; c < SS; c += 32) {
            float p = (c < lim) ? Sc[m][c] * rinv : 0.f;
            Sc[m][c] = p;                 // normalized probs for AV phase
            if (write_attn) arow[c] = p;
        }
    }

    // ---------------- phase 3: ctx = attn @ V -------------------------------
    float accc[2][4] = {};                // per warp: 2 m-tiles x (n = wid*8..+8)
    for (int kc = 0; kc < nch; kc++) {
        __syncthreads();                  // also orders softmax Sc writes before reads
        for (int i = tid; i < 128 * 16; i += 256) {
            int r = i >> 4, c4 = (i & 15) * 4;
            *(float4*)(&Ks[r][c4]) = *(const float4*)(vbase + (size_t)(kc * 128 + r) * DKK + c4);
        }
        __syncthreads();

        #pragma unroll
        for (int ks = 0; ks < 16; ks++) {
            const int kl  = ks * 8;
            const int kgl = kc * 128 + kl;
            uint32_t af[2][4], bf[2];
            #pragma unroll
            for (int im = 0; im < 2; im++) {
                int r = im * 16 + g;
                af[im][0] = f2tf(Sc[r    ][kgl + t    ]);
                af[im][1] = f2tf(Sc[r + 8][kgl + t    ]);
                af[im][2] = f2tf(Sc[r    ][kgl + t + 4]);
                af[im][3] = f2tf(Sc[r + 8][kgl + t + 4]);
            }
            bf[0] = f2tf(Ks[kl + t    ][wid * 8 + g]);
            bf[1] = f2tf(Ks[kl + t + 4][wid * 8 + g]);
            mma_tf32(accc[0], af[0], bf);
            mma_tf32(accc[1], af[1], bf);
        }
    }

    // store ctx [b*S+s][h*64+dh]
    #pragma unroll
    for (int im = 0; im < 2; im++) {
        int r = q0 + im * 16 + g;
        int c = h * 64 + wid * 8 + t * 2;
        *(float2*)(g_ctx + ((size_t)b * SS + r) * DD + c)     = make_float2(accc[im][0], accc[im][1]);
        *(float2*)(g_ctx + ((size_t)b * SS + r + 8) * DD + c) = make_float2(accc[im][2], accc[im][3]);
    }
}

// ---------------- launch -----------------------------------------------------
extern "C" void kernel_launch(void* const* d_in, const int* in_sizes, int n_in,
                              void* d_out, int out_size) {
    const float* Q  = (const float*)d_in[0];
    const float* K  = (const float*)d_in[1];
    const float* V  = (const float*)d_in[2];
    // d_in[3] = causal mask (int32) — structure is known, ignored
    const float* Wq = (const float*)d_in[4];  const float* bq = (const float*)d_in[5];
    const float* Wk = (const float*)d_in[6];  const float* bk = (const float*)d_in[7];
    const float* Wv = (const float*)d_in[8];  const float* bv = (const float*)d_in[9];
    const float* Wo = (const float*)d_in[10]; const float* bo = (const float*)d_in[11];

    float* out = (float*)d_out;
    const long long out_elems  = (long long)MTOT * DD;                  // 4,194,304
    const long long attn_elems = (long long)BB * HH * SS * SS;          // 67,108,864
    const int write_attn = ((long long)out_size >= out_elems + attn_elems) ? 1 : 0;
    float* attn = out + out_elems;

    cudaFuncSetAttribute(attn_kernel, cudaFuncAttributeMaxDynamicSharedMemorySize, ATTN_SMEM);

    dim3 gqkv(8, 32, 3);           // N/128 x M/128 x {q,k,v}
    gemm_qkv<<<gqkv, 256>>>(Q, K, V, Wq, Wk, Wv, bq, bk, bv);

    dim3 gatt(SS / 32, HH, BB);    // 32 q-tiles x 16 heads x 4 batch
    attn_kernel<<<gatt, 256, ATTN_SMEM>>>(attn, write_attn);

    dim3 gout(8, 32, 1);
    gemm_out<<<gout, 256>>>(Wo, bo, out);
}

// round 16
// speedup vs baseline: 1.3717x; 1.3717x over previous
#include <cuda_runtime.h>
#include <cuda_bf16.h>
#include <cstdint>

#define BB 4
#define SS 1024
#define HH 16
#define DKK 64
#define DD 1024
#define MTOT (BB*SS)

// ---------------- scratch (device globals; no allocations allowed) ----------
__device__ float g_q[BB*HH*SS*DKK];   // [b,h,s,dk]
__device__ float g_k[BB*HH*SS*DKK];
__device__ float g_v[BB*HH*SS*DKK];
__device__ float g_ctx[MTOT*DD];      // [b*S+s, h*64+dh]

// ---------------- helpers ----------------------------------------------------
__device__ __forceinline__ uint32_t f2tf(float f) {
    uint32_t r;
    asm("cvt.rna.tf32.f32 %0, %1;" : "=r"(r) : "f"(f));
    return r;
}

__device__ __forceinline__ void mma_tf32(float c[4], const uint32_t a[4], const uint32_t b[2]) {
    asm("mma.sync.aligned.m16n8k8.row.col.f32.tf32.tf32.f32 "
        "{%0,%1,%2,%3},{%4,%5,%6,%7},{%8,%9},{%0,%1,%2,%3};"
        : "+f"(c[0]), "+f"(c[1]), "+f"(c[2]), "+f"(c[3])
        : "r"(a[0]), "r"(a[1]), "r"(a[2]), "r"(a[3]), "r"(b[0]), "r"(b[1]));
}

__device__ __forceinline__ uint32_t smem_u32(const void* p) {
    return (uint32_t)__cvta_generic_to_shared(p);
}
__device__ __forceinline__ void cpa16(uint32_t s, const void* g) {
    asm volatile("cp.async.cg.shared.global [%0], [%1], 16;" :: "r"(s), "l"(g));
}
#define CP_COMMIT asm volatile("cp.async.commit_group;")
#define CP_WAIT1  asm volatile("cp.async.wait_group 1;")
#define CP_WAIT0  asm volatile("cp.async.wait_group 0;")

// ---------------- generic 128x128 tf32 GEMM body: C = X @ W^T + bias --------
// Double-buffered cp.async pipeline. X:[M,1024] rm, W:[N,1024] rm.
#define GT_PITCH 36
#define GT_TILE  (128 * GT_PITCH)          // floats per tile
#define GEMM_SMEM (4 * GT_TILE * 4)        // 2 stages x (A+B) = 73728 bytes

__device__ __forceinline__ void gemm_body(
    const float* __restrict__ X, const float* __restrict__ W,
    const float* __restrict__ bias,
    float* out4d, float* outRM, bool headsplit, float* sm)
{
    const int tid  = threadIdx.x;
    const int wid  = tid >> 5;
    const int lane = tid & 31;
    const int g    = lane >> 2;
    const int t    = lane & 3;
    const int wm   = (wid >> 2) * 64;
    const int wn   = (wid & 3) * 32;
    const int m0   = blockIdx.y * 128;
    const int n0   = blockIdx.x * 128;

    auto prefetch = [&](int s, int k0) {
        float* A = sm + s * 2 * GT_TILE;
        float* B = A + GT_TILE;
        #pragma unroll
        for (int p = 0; p < 4; p++) {
            int i  = tid + p * 256;
            int r  = i >> 3;
            int c4 = (i & 7) * 4;
            cpa16(smem_u32(A + r * GT_PITCH + c4), X + (size_t)(m0 + r) * 1024 + k0 + c4);
            cpa16(smem_u32(B + r * GT_PITCH + c4), W + (size_t)(n0 + r) * 1024 + k0 + c4);
        }
    };

    float acc[4][4][4] = {};

    prefetch(0, 0);
    CP_COMMIT;

    for (int it = 0; it < 32; it++) {
        const int cur = it & 1;
        if (it < 31) { prefetch(cur ^ 1, (it + 1) * 32); CP_COMMIT; CP_WAIT1; }
        else         { CP_WAIT0; }
        __syncthreads();

        const float* A = sm + cur * 2 * GT_TILE;
        const float* B = A + GT_TILE;

        #pragma unroll
        for (int ks = 0; ks < 4; ks++) {
            const int k = ks * 8;
            uint32_t af[4][4], bf[4][2];
            #pragma unroll
            for (int im = 0; im < 4; im++) {
                int r = wm + im * 16 + g;
                af[im][0] = f2tf(A[r * GT_PITCH + k + t]);
                af[im][1] = f2tf(A[(r + 8) * GT_PITCH + k + t]);
                af[im][2] = f2tf(A[r * GT_PITCH + k + t + 4]);
                af[im][3] = f2tf(A[(r + 8) * GT_PITCH + k + t + 4]);
            }
            #pragma unroll
            for (int in_ = 0; in_ < 4; in_++) {
                int c = wn + in_ * 8 + g;
                bf[in_][0] = f2tf(B[c * GT_PITCH + k + t]);
                bf[in_][1] = f2tf(B[c * GT_PITCH + k + t + 4]);
            }
            #pragma unroll
            for (int im = 0; im < 4; im++)
                #pragma unroll
                for (int in_ = 0; in_ < 4; in_++)
                    mma_tf32(acc[im][in_], af[im], bf[in_]);
        }
        __syncthreads();
    }

    // epilogue
    #pragma unroll
    for (int im = 0; im < 4; im++) {
        #pragma unroll
        for (int in_ = 0; in_ < 4; in_++) {
            int r0 = m0 + wm + im * 16 + g;
            int c0 = n0 + wn + in_ * 8 + t * 2;
            float bv0 = bias[c0], bv1 = bias[c0 + 1];
            float v00 = acc[im][in_][0] + bv0;
            float v01 = acc[im][in_][1] + bv1;
            float v10 = acc[im][in_][2] + bv0;
            float v11 = acc[im][in_][3] + bv1;
            if (headsplit) {
                #pragma unroll
                for (int rr = 0; rr < 2; rr++) {
                    int r = r0 + rr * 8;
                    int b = r >> 10, s = r & 1023;
                    int h = c0 >> 6, dh = c0 & 63;
                    size_t addr = ((((size_t)b * HH + h) * SS + s) * DKK + dh);
                    float2 v = rr ? make_float2(v10, v11) : make_float2(v00, v01);
                    *(float2*)(out4d + addr) = v;
                }
            } else {
                *(float2*)(outRM + (size_t)r0 * 1024 + c0)       = make_float2(v00, v01);
                *(float2*)(outRM + (size_t)(r0 + 8) * 1024 + c0) = make_float2(v10, v11);
            }
        }
    }
}

__global__ __launch_bounds__(256) void gemm_qkv(
    const float* __restrict__ Qin, const float* __restrict__ Kin, const float* __restrict__ Vin,
    const float* __restrict__ Wq, const float* __restrict__ Wk, const float* __restrict__ Wv,
    const float* __restrict__ bq, const float* __restrict__ bk, const float* __restrict__ bv)
{
    extern __shared__ float sm[];
    const float* X; const float* W; const float* bias; float* out;
    if (blockIdx.z == 0)      { X = Qin; W = Wq; bias = bq; out = g_q; }
    else if (blockIdx.z == 1) { X = Kin; W = Wk; bias = bk; out = g_k; }
    else                      { X = Vin; W = Wv; bias = bv; out = g_v; }
    gemm_body(X, W, bias, out, nullptr, true, sm);
}

__global__ __launch_bounds__(256) void gemm_out(
    const float* __restrict__ Wo, const float* __restrict__ bo, float* __restrict__ out)
{
    extern __shared__ float sm[];
    gemm_body(g_ctx, Wo, bo, nullptr, out, false, sm);
}

// ---------------- attention kernel ------------------------------------------
// One CTA per (b, h, 32-row q-tile). 256 threads.
// smem: Qs[32][68] | Ks[2][128][68] (K then reused for V, double-buffered) | Sc[32][1036]
#define QS_PITCH 68
#define KS_PITCH 68
#define SC_PITCH 1036
#define QS_ELEMS (32 * QS_PITCH)
#define KS_ELEMS (128 * KS_PITCH)
#define SC_ELEMS (32 * SC_PITCH)
#define ATTN_SMEM ((QS_ELEMS + 2 * KS_ELEMS + SC_ELEMS) * 4)   // 210944 bytes

__global__ __launch_bounds__(256, 1) void attn_kernel(float* __restrict__ attn_out, int write_attn)
{
    extern __shared__ float sm[];
    float* Qs   = sm;
    float* Ksb  = sm + QS_ELEMS;
    float (*Sc)[SC_PITCH] = (float(*)[SC_PITCH])(sm + QS_ELEMS + 2 * KS_ELEMS);

    const int tid  = threadIdx.x;
    const int wid  = tid >> 5;
    const int lane = tid & 31;
    const int g    = lane >> 2;
    const int t    = lane & 3;
    const int b    = blockIdx.z;
    const int h    = blockIdx.y;
    const int qt   = gridDim.x - 1 - blockIdx.x;   // heavy tiles first
    const int q0   = qt * 32;

    const size_t bh = (size_t)b * HH + h;
    const float* qbase = g_q + bh * SS * DKK;
    const float* kbase = g_k + bh * SS * DKK;
    const float* vbase = g_v + bh * SS * DKK;

    const int kmax = q0 + 32;
    const int nch  = (kmax + 127) >> 7;

    auto cpchunk = [&](int s, const float* base, int kc) {
        float* T = Ksb + s * KS_ELEMS;
        #pragma unroll
        for (int p = 0; p < 8; p++) {
            int i  = tid + p * 256;
            int r  = i >> 4;
            int c4 = (i & 15) * 4;
            cpa16(smem_u32(T + r * KS_PITCH + c4), base + (size_t)(kc * 128 + r) * DKK + c4);
        }
    };

    // ---- prefetch Q tile + K chunk 0 (one group) ----
    #pragma unroll
    for (int p = 0; p < 2; p++) {
        int i  = tid + p * 256;
        int r  = i >> 4;
        int c4 = (i & 15) * 4;
        cpa16(smem_u32(Qs + r * QS_PITCH + c4), qbase + (size_t)(q0 + r) * DKK + c4);
    }
    cpchunk(0, kbase, 0);
    CP_COMMIT;

    uint32_t afq[8][2][4];   // Q fragments, loop-invariant across chunks

    // ---------------- phase 1: scores = Q K^T / 8 into Sc -------------------
    for (int kc = 0; kc < nch; kc++) {
        const int cur = kc & 1;
        if (kc + 1 < nch) { cpchunk(cur ^ 1, kbase, kc + 1); CP_COMMIT; CP_WAIT1; }
        else              { CP_WAIT0; }
        __syncthreads();

        if (kc == 0) {
            #pragma unroll
            for (int ks = 0; ks < 8; ks++) {
                const int k = ks * 8;
                #pragma unroll
                for (int im = 0; im < 2; im++) {
                    int r = im * 16 + g;
                    afq[ks][im][0] = f2tf(Qs[r * QS_PITCH + k + t]);
                    afq[ks][im][1] = f2tf(Qs[(r + 8) * QS_PITCH + k + t]);
                    afq[ks][im][2] = f2tf(Qs[r * QS_PITCH + k + t + 4]);
                    afq[ks][im][3] = f2tf(Qs[(r + 8) * QS_PITCH + k + t + 4]);
                }
            }
        }

        const float* KK = Ksb + cur * KS_ELEMS;
        float acc[2][2][4] = {};
        #pragma unroll
        for (int ks = 0; ks < 8; ks++) {
            const int k = ks * 8;
            uint32_t bf[2][2];
            #pragma unroll
            for (int in_ = 0; in_ < 2; in_++) {
                int c = wid * 16 + in_ * 8 + g;
                bf[in_][0] = f2tf(KK[c * KS_PITCH + k + t]);
                bf[in_][1] = f2tf(KK[c * KS_PITCH + k + t + 4]);
            }
            #pragma unroll
            for (int im = 0; im < 2; im++)
                #pragma unroll
                for (int in_ = 0; in_ < 2; in_++)
                    mma_tf32(acc[im][in_], afq[ks][im], bf[in_]);
        }
        #pragma unroll
        for (int im = 0; im < 2; im++) {
            #pragma unroll
            for (int in_ = 0; in_ < 2; in_++) {
                int r = im * 16 + g;
                int c = kc * 128 + wid * 16 + in_ * 8 + t * 2;
                *(float2*)(&Sc[r    ][c]) = make_float2(acc[im][in_][0] * 0.125f, acc[im][in_][1] * 0.125f);
                *(float2*)(&Sc[r + 8][c]) = make_float2(acc[im][in_][2] * 0.125f, acc[im][in_][3] * 0.125f);
            }
        }
        __syncthreads();
    }

    // prefetch V chunk 0 under the softmax phase
    cpchunk(0, vbase, 0);
    CP_COMMIT;

    // ---------------- phase 2: causal softmax + write attn ------------------
    #pragma unroll
    for (int rr = 0; rr < 4; rr++) {
        const int m   = wid + rr * 8;
        const int q   = q0 + m;
        const int lim = q + 1;

        float mx = -3.4e38f;
        for (int c = lane; c < lim; c += 32) mx = fmaxf(mx, Sc[m][c]);
        #pragma unroll
        for (int o = 16; o; o >>= 1) mx = fmaxf(mx, __shfl_xor_sync(0xffffffffu, mx, o));

        float s = 0.f;
        for (int c = lane; c < lim; c += 32) {
            float e = __expf(Sc[m][c] - mx);
            Sc[m][c] = e;
            s += e;
        }
        #pragma unroll
        for (int o = 16; o; o >>= 1) s += __shfl_xor_sync(0xffffffffu, s, o);
        const float rinv = 1.0f / s;

        float* arow = attn_out + (bh * SS + (size_t)q) * SS;
        for (int c = lane; c < SS; c += 32) {
            float p = (c < lim) ? Sc[m][c] * rinv : 0.f;
            Sc[m][c] = __uint_as_float(f2tf(p));   // tf32-rounded for AV MMA
            if (write_attn) arow[c] = p;            // full precision to output
        }
    }
    __syncthreads();

    // ---------------- phase 3: ctx = attn @ V -------------------------------
    float accc[2][4] = {};
    for (int kc = 0; kc < nch; kc++) {
        const int cur = kc & 1;
        if (kc + 1 < nch) { cpchunk(cur ^ 1, vbase, kc + 1); CP_COMMIT; CP_WAIT1; }
        else              { CP_WAIT0; }
        __syncthreads();

        const float* VV = Ksb + cur * KS_ELEMS;
        #pragma unroll
        for (int ks = 0; ks < 16; ks++) {
            const int kl  = ks * 8;
            const int kgl = kc * 128 + kl;
            uint32_t af[2][4], bf[2];
            #pragma unroll
            for (int im = 0; im < 2; im++) {
                int r = im * 16 + g;
                af[im][0] = __float_as_uint(Sc[r    ][kgl + t    ]);
                af[im][1] = __float_as_uint(Sc[r + 8][kgl + t    ]);
                af[im][2] = __float_as_uint(Sc[r    ][kgl + t + 4]);
                af[im][3] = __float_as_uint(Sc[r + 8][kgl + t + 4]);
            }
            bf[0] = f2tf(VV[(kl + t    ) * KS_PITCH + wid * 8 + g]);
            bf[1] = f2tf(VV[(kl + t + 4) * KS_PITCH + wid * 8 + g]);
            mma_tf32(accc[0], af[0], bf);
            mma_tf32(accc[1], af[1], bf);
        }
        __syncthreads();
    }

    // store ctx [b*S+s][h*64+dh]
    #pragma unroll
    for (int im = 0; im < 2; im++) {
        int r = q0 + im * 16 + g;
        int c = h * 64 + wid * 8 + t * 2;
        *(float2*)(g_ctx + ((size_t)b * SS + r) * DD + c)     = make_float2(accc[im][0], accc[im][1]);
        *(float2*)(g_ctx + ((size_t)b * SS + r + 8) * DD + c) = make_float2(accc[im][2], accc[im][3]);
    }
}

// ---------------- launch -----------------------------------------------------
extern "C" void kernel_launch(void* const* d_in, const int* in_sizes, int n_in,
                              void* d_out, int out_size) {
    const float* Q  = (const float*)d_in[0];
    const float* K  = (const float*)d_in[1];
    const float* V  = (const float*)d_in[2];
    // d_in[3] = causal mask (int32) — structure known, ignored
    const float* Wq = (const float*)d_in[4];  const float* bq = (const float*)d_in[5];
    const float* Wk = (const float*)d_in[6];  const float* bk = (const float*)d_in[7];
    const float* Wv = (const float*)d_in[8];  const float* bv = (const float*)d_in[9];
    const float* Wo = (const float*)d_in[10]; const float* bo = (const float*)d_in[11];

    float* out = (float*)d_out;
    const long long out_elems  = (long long)MTOT * DD;
    const long long attn_elems = (long long)BB * HH * SS * SS;
    const int write_attn = ((long long)out_size >= out_elems + attn_elems) ? 1 : 0;
    float* attn = out + out_elems;

    static int configured = 0;
    if (!configured) {
        cudaFuncSetAttribute(gemm_qkv,   cudaFuncAttributeMaxDynamicSharedMemorySize, GEMM_SMEM);
        cudaFuncSetAttribute(gemm_out,   cudaFuncAttributeMaxDynamicSharedMemorySize, GEMM_SMEM);
        cudaFuncSetAttribute(attn_kernel, cudaFuncAttributeMaxDynamicSharedMemorySize, ATTN_SMEM);
        configured = 1;
    }

    dim3 gqkv(8, 32, 3);
    gemm_qkv<<<gqkv, 256, GEMM_SMEM>>>(Q, K, V, Wq, Wk, Wv, bq, bk, bv);

    dim3 gatt(SS / 32, HH, BB);
    attn_kernel<<<gatt, 256, ATTN_SMEM>>>(attn, write_attn);

    dim3 gout(8, 32, 1);
    gemm_out<<<gout, 256, GEMM_SMEM>>>(Wo, bo, out);
}

// round 17
// speedup vs baseline: 1.3739x; 1.0016x over previous
#include <cuda_runtime.h>
#include <cuda_bf16.h>
#include <cstdint>

#define BB 4
#define SS 1024
#define HH 16
#define DKK 64
#define DD 1024
#define MTOT (BB*SS)

// ---------------- scratch (device globals; no allocations allowed) ----------
__device__ float g_q[BB*HH*SS*DKK];   // [b,h,s,dk]
__device__ float g_k[BB*HH*SS*DKK];
__device__ float g_v[BB*HH*SS*DKK];
__device__ float g_ctx[MTOT*DD];      // [b*S+s, h*64+dh]

// ---------------- helpers ----------------------------------------------------
__device__ __forceinline__ uint32_t f2tf(float f) {
    uint32_t r;
    asm("cvt.rna.tf32.f32 %0, %1;" : "=r"(r) : "f"(f));
    return r;
}

__device__ __forceinline__ void mma_tf32(float c[4], const uint32_t a[4], const uint32_t b[2]) {
    asm("mma.sync.aligned.m16n8k8.row.col.f32.tf32.tf32.f32 "
        "{%0,%1,%2,%3},{%4,%5,%6,%7},{%8,%9},{%0,%1,%2,%3};"
        : "+f"(c[0]), "+f"(c[1]), "+f"(c[2]), "+f"(c[3])
        : "r"(a[0]), "r"(a[1]), "r"(a[2]), "r"(a[3]), "r"(b[0]), "r"(b[1]));
}

__device__ __forceinline__ uint32_t smem_u32(const void* p) {
    return (uint32_t)__cvta_generic_to_shared(p);
}
__device__ __forceinline__ void cpa16(uint32_t s, const void* g) {
    asm volatile("cp.async.cg.shared.global [%0], [%1], 16;" :: "r"(s), "l"(g));
}
#define CP_COMMIT asm volatile("cp.async.commit_group;")
#define CP_WAIT1  asm volatile("cp.async.wait_group 1;")
#define CP_WAIT0  asm volatile("cp.async.wait_group 0;")

// ---------------- generic 128x128 tf32 GEMM body: C = X @ W^T + bias --------
// Double-buffered cp.async pipeline. X:[M,1024] rm, W:[N,1024] rm.
#define GT_PITCH 36
#define GT_TILE  (128 * GT_PITCH)          // floats per tile
#define GEMM_SMEM (4 * GT_TILE * 4)        // 2 stages x (A+B) = 73728 bytes

__device__ __forceinline__ void gemm_body(
    const float* __restrict__ X, const float* __restrict__ W,
    const float* __restrict__ bias,
    float* out4d, float* outRM, bool headsplit, float* sm)
{
    const int tid  = threadIdx.x;
    const int wid  = tid >> 5;
    const int lane = tid & 31;
    const int g    = lane >> 2;
    const int t    = lane & 3;
    const int wm   = (wid >> 2) * 64;
    const int wn   = (wid & 3) * 32;
    const int m0   = blockIdx.y * 128;
    const int n0   = blockIdx.x * 128;

    auto prefetch = [&](int s, int k0) {
        float* A = sm + s * 2 * GT_TILE;
        float* B = A + GT_TILE;
        #pragma unroll
        for (int p = 0; p < 4; p++) {
            int i  = tid + p * 256;
            int r  = i >> 3;
            int c4 = (i & 7) * 4;
            cpa16(smem_u32(A + r * GT_PITCH + c4), X + (size_t)(m0 + r) * 1024 + k0 + c4);
            cpa16(smem_u32(B + r * GT_PITCH + c4), W + (size_t)(n0 + r) * 1024 + k0 + c4);
        }
    };

    float acc[4][4][4] = {};

    prefetch(0, 0);
    CP_COMMIT;

    for (int it = 0; it < 32; it++) {
        const int cur = it & 1;
        if (it < 31) { prefetch(cur ^ 1, (it + 1) * 32); CP_COMMIT; CP_WAIT1; }
        else         { CP_WAIT0; }
        __syncthreads();

        const float* A = sm + cur * 2 * GT_TILE;
        const float* B = A + GT_TILE;

        #pragma unroll
        for (int ks = 0; ks < 4; ks++) {
            const int k = ks * 8;
            uint32_t af[4][4], bf[4][2];
            #pragma unroll
            for (int im = 0; im < 4; im++) {
                int r = wm + im * 16 + g;
                af[im][0] = f2tf(A[r * GT_PITCH + k + t]);
                af[im][1] = f2tf(A[(r + 8) * GT_PITCH + k + t]);
                af[im][2] = f2tf(A[r * GT_PITCH + k + t + 4]);
                af[im][3] = f2tf(A[(r + 8) * GT_PITCH + k + t + 4]);
            }
            #pragma unroll
            for (int in_ = 0; in_ < 4; in_++) {
                int c = wn + in_ * 8 + g;
                bf[in_][0] = f2tf(B[c * GT_PITCH + k + t]);
                bf[in_][1] = f2tf(B[c * GT_PITCH + k + t + 4]);
            }
            #pragma unroll
            for (int im = 0; im < 4; im++)
                #pragma unroll
                for (int in_ = 0; in_ < 4; in_++)
                    mma_tf32(acc[im][in_], af[im], bf[in_]);
        }
        __syncthreads();
    }

    // epilogue
    #pragma unroll
    for (int im = 0; im < 4; im++) {
        #pragma unroll
        for (int in_ = 0; in_ < 4; in_++) {
            int r0 = m0 + wm + im * 16 + g;
            int c0 = n0 + wn + in_ * 8 + t * 2;
            float bv0 = bias[c0], bv1 = bias[c0 + 1];
            float v00 = acc[im][in_][0] + bv0;
            float v01 = acc[im][in_][1] + bv1;
            float v10 = acc[im][in_][2] + bv0;
            float v11 = acc[im][in_][3] + bv1;
            if (headsplit) {
                #pragma unroll
                for (int rr = 0; rr < 2; rr++) {
                    int r = r0 + rr * 8;
                    int b = r >> 10, s = r & 1023;
                    int h = c0 >> 6, dh = c0 & 63;
                    size_t addr = ((((size_t)b * HH + h) * SS + s) * DKK + dh);
                    float2 v = rr ? make_float2(v10, v11) : make_float2(v00, v01);
                    *(float2*)(out4d + addr) = v;
                }
            } else {
                *(float2*)(outRM + (size_t)r0 * 1024 + c0)       = make_float2(v00, v01);
                *(float2*)(outRM + (size_t)(r0 + 8) * 1024 + c0) = make_float2(v10, v11);
            }
        }
    }
}

__global__ __launch_bounds__(256) void gemm_qkv(
    const float* __restrict__ Qin, const float* __restrict__ Kin, const float* __restrict__ Vin,
    const float* __restrict__ Wq, const float* __restrict__ Wk, const float* __restrict__ Wv,
    const float* __restrict__ bq, const float* __restrict__ bk, const float* __restrict__ bv)
{
    extern __shared__ float sm[];
    const float* X; const float* W; const float* bias; float* out;
    if (blockIdx.z == 0)      { X = Qin; W = Wq; bias = bq; out = g_q; }
    else if (blockIdx.z == 1) { X = Kin; W = Wk; bias = bk; out = g_k; }
    else                      { X = Vin; W = Wv; bias = bv; out = g_v; }
    gemm_body(X, W, bias, out, nullptr, true, sm);
}

__global__ __launch_bounds__(256) void gemm_out(
    const float* __restrict__ Wo, const float* __restrict__ bo, float* __restrict__ out)
{
    extern __shared__ float sm[];
    gemm_body(g_ctx, Wo, bo, nullptr, out, false, sm);
}

// ---------------- attention kernel ------------------------------------------
// One CTA per (b, h, 32-row q-tile). 256 threads.
// smem: Qs[32][68] | Ks[2][128][68] (K then reused for V, double-buffered) | Sc[32][1036]
#define QS_PITCH 68
#define KS_PITCH 68
#define SC_PITCH 1036
#define QS_ELEMS (32 * QS_PITCH)
#define KS_ELEMS (128 * KS_PITCH)
#define SC_ELEMS (32 * SC_PITCH)
#define ATTN_SMEM ((QS_ELEMS + 2 * KS_ELEMS + SC_ELEMS) * 4)   // 210944 bytes

__global__ __launch_bounds__(256, 1) void attn_kernel(float* __restrict__ attn_out, int write_attn)
{
    extern __shared__ float sm[];
    float* Qs   = sm;
    float* Ksb  = sm + QS_ELEMS;
    float (*Sc)[SC_PITCH] = (float(*)[SC_PITCH])(sm + QS_ELEMS + 2 * KS_ELEMS);

    const int tid  = threadIdx.x;
    const int wid  = tid >> 5;
    const int lane = tid & 31;
    const int g    = lane >> 2;
    const int t    = lane & 3;
    const int b    = blockIdx.z;
    const int h    = blockIdx.y;
    const int qt   = gridDim.x - 1 - blockIdx.x;   // heavy tiles first
    const int q0   = qt * 32;

    const size_t bh = (size_t)b * HH + h;
    const float* qbase = g_q + bh * SS * DKK;
    const float* kbase = g_k + bh * SS * DKK;
    const float* vbase = g_v + bh * SS * DKK;

    const int kmax = q0 + 32;
    const int nch  = (kmax + 127) >> 7;

    auto cpchunk = [&](int s, const float* base, int kc) {
        float* T = Ksb + s * KS_ELEMS;
        #pragma unroll
        for (int p = 0; p < 8; p++) {
            int i  = tid + p * 256;
            int r  = i >> 4;
            int c4 = (i & 15) * 4;
            cpa16(smem_u32(T + r * KS_PITCH + c4), base + (size_t)(kc * 128 + r) * DKK + c4);
        }
    };

    // ---- prefetch Q tile + K chunk 0 (one group) ----
    #pragma unroll
    for (int p = 0; p < 2; p++) {
        int i  = tid + p * 256;
        int r  = i >> 4;
        int c4 = (i & 15) * 4;
        cpa16(smem_u32(Qs + r * QS_PITCH + c4), qbase + (size_t)(q0 + r) * DKK + c4);
    }
    cpchunk(0, kbase, 0);
    CP_COMMIT;

    uint32_t afq[8][2][4];   // Q fragments, loop-invariant across chunks

    // ---------------- phase 1: scores = Q K^T / 8 into Sc -------------------
    for (int kc = 0; kc < nch; kc++) {
        const int cur = kc & 1;
        if (kc + 1 < nch) { cpchunk(cur ^ 1, kbase, kc + 1); CP_COMMIT; CP_WAIT1; }
        else              { CP_WAIT0; }
        __syncthreads();

        if (kc == 0) {
            #pragma unroll
            for (int ks = 0; ks < 8; ks++) {
                const int k = ks * 8;
                #pragma unroll
                for (int im = 0; im < 2; im++) {
                    int r = im * 16 + g;
                    afq[ks][im][0] = f2tf(Qs[r * QS_PITCH + k + t]);
                    afq[ks][im][1] = f2tf(Qs[(r + 8) * QS_PITCH + k + t]);
                    afq[ks][im][2] = f2tf(Qs[r * QS_PITCH + k + t + 4]);
                    afq[ks][im][3] = f2tf(Qs[(r + 8) * QS_PITCH + k + t + 4]);
                }
            }
        }

        const float* KK = Ksb + cur * KS_ELEMS;
        float acc[2][2][4] = {};
        #pragma unroll
        for (int ks = 0; ks < 8; ks++) {
            const int k = ks * 8;
            uint32_t bf[2][2];
            #pragma unroll
            for (int in_ = 0; in_ < 2; in_++) {
                int c = wid * 16 + in_ * 8 + g;
                bf[in_][0] = f2tf(KK[c * KS_PITCH + k + t]);
                bf[in_][1] = f2tf(KK[c * KS_PITCH + k + t + 4]);
            }
            #pragma unroll
            for (int im = 0; im < 2; im++)
                #pragma unroll
                for (int in_ = 0; in_ < 2; in_++)
                    mma_tf32(acc[im][in_], afq[ks][im], bf[in_]);
        }
        #pragma unroll
        for (int im = 0; im < 2; im++) {
            #pragma unroll
            for (int in_ = 0; in_ < 2; in_++) {
                int r = im * 16 + g;
                int c = kc * 128 + wid * 16 + in_ * 8 + t * 2;
                *(float2*)(&Sc[r    ][c]) = make_float2(acc[im][in_][0] * 0.125f, acc[im][in_][1] * 0.125f);
                *(float2*)(&Sc[r + 8][c]) = make_float2(acc[im][in_][2] * 0.125f, acc[im][in_][3] * 0.125f);
            }
        }
        __syncthreads();
    }

    // prefetch V chunk 0 under the softmax phase
    cpchunk(0, vbase, 0);
    CP_COMMIT;

    // ---------------- phase 2: causal softmax + write attn ------------------
    #pragma unroll
    for (int rr = 0; rr < 4; rr++) {
        const int m   = wid + rr * 8;
        const int q   = q0 + m;
        const int lim = q + 1;

        float mx = -3.4e38f;
        for (int c = lane; c < lim; c += 32) mx = fmaxf(mx, Sc[m][c]);
        #pragma unroll
        for (int o = 16; o; o >>= 1) mx = fmaxf(mx, __shfl_xor_sync(0xffffffffu, mx, o));

        float s = 0.f;
        for (int c = lane; c < lim; c += 32) {
            float e = __expf(Sc[m][c] - mx);
            Sc[m][c] = e;
            s += e;
        }
        #pragma unroll
        for (int o = 16; o; o >>= 1) s += __shfl_xor_sync(0xffffffffu, s, o);
        const float rinv = 1.0f / s;

        float* arow = attn_out + (bh * SS + (size_t)q) * SS;
        for (int c = lane; c < SS; c += 32) {
            float p = (c < lim) ? Sc[m][c] * rinv : 0.f;
            Sc[m][c] = __uint_as_float(f2tf(p));   // tf32-rounded for AV MMA
            if (write_attn) arow[c] = p;            // full precision to output
        }
    }
    __syncthreads();

    // ---------------- phase 3: ctx = attn @ V -------------------------------
    float accc[2][4] = {};
    for (int kc = 0; kc < nch; kc++) {
        const int cur = kc & 1;
        if (kc + 1 < nch) { cpchunk(cur ^ 1, vbase, kc + 1); CP_COMMIT; CP_WAIT1; }
        else              { CP_WAIT0; }
        __syncthreads();

        const float* VV = Ksb + cur * KS_ELEMS;
        #pragma unroll
        for (int ks = 0; ks < 16; ks++) {
            const int kl  = ks * 8;
            const int kgl = kc * 128 + kl;
            uint32_t af[2][4], bf[2];
            #pragma unroll
            for (int im = 0; im < 2; im++) {
                int r = im * 16 + g;
                af[im][0] = __float_as_uint(Sc[r    ][kgl + t    ]);
                af[im][1] = __float_as_uint(Sc[r + 8][kgl + t    ]);
                af[im][2] = __float_as_uint(Sc[r    ][kgl + t + 4]);
                af[im][3] = __float_as_uint(Sc[r + 8][kgl + t + 4]);
            }
            bf[0] = f2tf(VV[(kl + t    ) * KS_PITCH + wid * 8 + g]);
            bf[1] = f2tf(VV[(kl + t + 4) * KS_PITCH + wid * 8 + g]);
            mma_tf32(accc[0], af[0], bf);
            mma_tf32(accc[1], af[1], bf);
        }
        __syncthreads();
    }

    // store ctx [b*S+s][h*64+dh]
    #pragma unroll
    for (int im = 0; im < 2; im++) {
        int r = q0 + im * 16 + g;
        int c = h * 64 + wid * 8 + t * 2;
        *(float2*)(g_ctx + ((size_t)b * SS + r) * DD + c)     = make_float2(accc[im][0], accc[im][1]);
        *(float2*)(g_ctx + ((size_t)b * SS + r + 8) * DD + c) = make_float2(accc[im][2], accc[im][3]);
    }
}

// ---------------- launch -----------------------------------------------------
extern "C" void kernel_launch(void* const* d_in, const int* in_sizes, int n_in,
                              void* d_out, int out_size) {
    const float* Q  = (const float*)d_in[0];
    const float* K  = (const float*)d_in[1];
    const float* V  = (const float*)d_in[2];
    // d_in[3] = causal mask (int32) — structure known, ignored
    const float* Wq = (const float*)d_in[4];  const float* bq = (const float*)d_in[5];
    const float* Wk = (const float*)d_in[6];  const float* bk = (const float*)d_in[7];
    const float* Wv = (const float*)d_in[8];  const float* bv = (const float*)d_in[9];
    const float* Wo = (const float*)d_in[10]; const float* bo = (const float*)d_in[11];

    float* out = (float*)d_out;
    const long long out_elems  = (long long)MTOT * DD;
    const long long attn_elems = (long long)BB * HH * SS * SS;
    const int write_attn = ((long long)out_size >= out_elems + attn_elems) ? 1 : 0;
    float* attn = out + out_elems;

    static int configured = 0;
    if (!configured) {
        cudaFuncSetAttribute(gemm_qkv,   cudaFuncAttributeMaxDynamicSharedMemorySize, GEMM_SMEM);
        cudaFuncSetAttribute(gemm_out,   cudaFuncAttributeMaxDynamicSharedMemorySize, GEMM_SMEM);
        cudaFuncSetAttribute(attn_kernel, cudaFuncAttributeMaxDynamicSharedMemorySize, ATTN_SMEM);
        configured = 1;
    }

    dim3 gqkv(8, 32, 3);
    gemm_qkv<<<gqkv, 256, GEMM_SMEM>>>(Q, K, V, Wq, Wk, Wv, bq, bk, bv);

    dim3 gatt(SS / 32, HH, BB);
    attn_kernel<<<gatt, 256, ATTN_SMEM>>>(attn, write_attn);

    dim3 gout(8, 32, 1);
    gemm_out<<<gout, 256, GEMM_SMEM>>>(Wo, bo, out);
}